// round 9
// baseline (speedup 1.0000x reference)
#include <cuda_runtime.h>
#include <math.h>

// Problem constants
#define BB   256
#define TT   512
#define IND  128
#define NI   149
#define NC   99
#define NM   8
#define CAT0 (IND + NI)   // 277
#define CAT1 (NI + NC)    // 248
#define CAT2 (NC + NM)    // 107
#define S0   160
#define S1   128
#define S2   8
#define K0P  280          // 8 chunks x 35
#define K1P  252          // 12 chunks x 21
#define ROWS 4
#define NTH  480

// SMEM layout (floats). xh0/xh1 are double-buffered (ping-pong by step parity).
#define XB0       2240
#define XB1       2016
#define OFF_XH0   0                  // 2 x 2240
#define OFF_XH1   4480               // 2 x 2016
#define OFF_XH2   8512               // 448
#define OFF_PART  8960               // 7680
#define OFF_PART2 16640              // 1920
#define OFF_SW2   18560              // 2568
#define OFF_MBAR  21128              // 2 mbarriers (4 floats used)
#define SMEM_FLOATS 21136
#define SMEM_BYTES  (SMEM_FLOATS * 4)

#define MB_FL0  (OFF_MBAR + 0)
#define MB_FL1  (OFF_MBAR + 2)

__device__ float g_W0[3][K0P * S0];
__device__ float g_W1[3][K1P * S1];
__device__ float g_W2[3][CAT2 * S2];
__device__ float g_bc[NI + NC + NM];

// ---------------------------------------------------------------------------
__global__ void cfc_precompute_kernel(
    const float* __restrict__ w1_0, const float* __restrict__ w2_0,
    const float* __restrict__ wa_0, const float* __restrict__ wb_0,
    const float* __restrict__ ba_0, const float* __restrict__ bb_0,
    const int*   __restrict__ m0,
    const float* __restrict__ w1_1, const float* __restrict__ w2_1,
    const float* __restrict__ wa_1, const float* __restrict__ wb_1,
    const float* __restrict__ ba_1, const float* __restrict__ bb_1,
    const int*   __restrict__ m1,
    const float* __restrict__ w1_2, const float* __restrict__ w2_2,
    const float* __restrict__ wa_2, const float* __restrict__ wb_2,
    const float* __restrict__ ba_2, const float* __restrict__ bb_2,
    const int*   __restrict__ m2,
    const float* __restrict__ dt)
{
    const float ts = dt[0];
    const int idx    = blockIdx.x * blockDim.x + threadIdx.x;
    const int stride = gridDim.x * blockDim.x;

    for (int i = idx; i < K0P * S0; i += stride) {
        int k = i / S0, j = i - k * S0;
        float v1 = 0.f, v2 = 0.f, vc = 0.f;
        if (j < NI && k < CAT0) {
            int src = j * CAT0 + k;
            float mm = (float)m0[src];
            v1 = w1_0[src] * mm;
            v2 = w2_0[src] * mm;
            vc = ts * wa_0[src] + wb_0[src];
        }
        g_W0[0][i] = v1; g_W0[1][i] = v2; g_W0[2][i] = vc;
    }
    for (int i = idx; i < K1P * S1; i += stride) {
        int k = i / S1, j = i - k * S1;
        float v1 = 0.f, v2 = 0.f, vc = 0.f;
        if (j < NC && k < CAT1) {
            int src = j * CAT1 + k;
            float mm = (float)m1[src];
            v1 = w1_1[src] * mm;
            v2 = w2_1[src] * mm;
            vc = ts * wa_1[src] + wb_1[src];
        }
        g_W1[0][i] = v1; g_W1[1][i] = v2; g_W1[2][i] = vc;
    }
    for (int i = idx; i < CAT2 * S2; i += stride) {
        int k = i / S2, j = i - k * S2;
        int src = j * CAT2 + k;
        float mm = (float)m2[src];
        g_W2[0][i] = w1_2[src] * mm;
        g_W2[1][i] = w2_2[src] * mm;
        g_W2[2][i] = ts * wa_2[src] + wb_2[src];
    }
    for (int j = idx; j < NI; j += stride) g_bc[j]           = ts * ba_0[j] + bb_0[j];
    for (int j = idx; j < NC; j += stride) g_bc[NI + j]      = ts * ba_1[j] + bb_1[j];
    for (int j = idx; j < NM; j += stride) g_bc[NI + NC + j] = ts * ba_2[j] + bb_2[j];
}

// ---------------------------------------------------------------------------
__device__ __forceinline__ unsigned long long pack2(float a, float b) {
    unsigned long long r;
    asm("mov.b64 %0, {%1, %2};" : "=l"(r) : "f"(a), "f"(b));
    return r;
}
__device__ __forceinline__ void unpack2(unsigned long long v, float& a, float& b) {
    asm("mov.b64 {%0, %1}, %2;" : "=f"(a), "=f"(b) : "l"(v));
}
__device__ __forceinline__ unsigned long long fma2(unsigned long long a,
                                                   unsigned long long b,
                                                   unsigned long long c) {
    unsigned long long d;
    asm("fma.rn.f32x2 %0, %1, %2, %3;" : "=l"(d) : "l"(a), "l"(b), "l"(c));
    return d;
}
__device__ __forceinline__ unsigned long long add2(unsigned long long a,
                                                   unsigned long long b) {
    unsigned long long d;
    asm("add.rn.f32x2 %0, %1, %2;" : "=l"(d) : "l"(a), "l"(b));
    return d;
}
__device__ __forceinline__ float sigmoidf_(float z) { return 1.0f / (1.0f + expf(-z)); }
__device__ __forceinline__ float cfc_mix(float a1, float a2, float ac,
                                         float b1, float b2, float bc) {
    float ff1 = tanhf(a1 + b1);
    float ff2 = tanhf(a2 + b2);
    float ti  = sigmoidf_(ac + bc);
    return ff1 + ti * (ff2 - ff1);
}
__device__ __forceinline__ unsigned smem_u32(const void* p) {
    unsigned a;
    asm("{ .reg .u64 t; cvta.to.shared.u64 t, %1; cvt.u32.u64 %0, t; }"
        : "=r"(a) : "l"(p));
    return a;
}
__device__ __forceinline__ void mbar_init(unsigned addr, unsigned count) {
    asm volatile("mbarrier.init.shared.b64 [%0], %1;" :: "r"(addr), "r"(count) : "memory");
}
__device__ __forceinline__ void mbar_wait(unsigned addr, unsigned parity) {
    unsigned done = 0;
    do {
        asm volatile(
            "{\n\t.reg .pred P;\n\t"
            "mbarrier.try_wait.parity.acquire.cluster.shared::cta.b64 P, [%1], %2, 0x989680;\n\t"
            "selp.b32 %0, 1, 0, P;\n\t}"
            : "=r"(done) : "r"(addr), "r"(parity) : "memory");
    } while (!done);
}
__device__ __forceinline__ void mbar_arrive_peer(unsigned addr, unsigned peer) {
    asm volatile(
        "{\n\t.reg .b32 ra;\n\t"
        "mapa.shared::cluster.u32 ra, %0, %1;\n\t"
        "mbarrier.arrive.release.cluster.shared::cluster.b64 _, [ra];\n\t}"
        :: "r"(addr), "r"(peer) : "memory");
}
__device__ __forceinline__ void fence_arrive_peer(unsigned addr, unsigned peer) {
    asm volatile("fence.acq_rel.cluster;" ::: "memory");
    mbar_arrive_peer(addr, peer);
}
__device__ __forceinline__ void st_peer_u64(unsigned addr, unsigned peer,
                                            unsigned long long v) {
    asm volatile(
        "{\n\t.reg .b32 ra;\n\t"
        "mapa.shared::cluster.u32 ra, %0, %1;\n\t"
        "st.shared::cluster.u64 [ra], %2;\n\t}"
        :: "r"(addr), "r"(peer), "l"(v) : "memory");
}
__device__ __forceinline__ void st_peer_u32(unsigned addr, unsigned peer, float v) {
    asm volatile(
        "{\n\t.reg .b32 ra;\n\t"
        "mapa.shared::cluster.u32 ra, %0, %1;\n\t"
        "st.shared::cluster.f32 [ra], %2;\n\t}"
        :: "r"(addr), "r"(peer), "f"(v) : "memory");
}

// ---------------------------------------------------------------------------
// 64 clusters x 2 CTAs, 4 batch rows/cluster, j split 2 ways.
// Ping-pong xh0/xh1 removes all reader-done gates; one tid0 handshake per
// exchange (fence + remote release-arrive + acquire wait), others bar.sync.
// ---------------------------------------------------------------------------
__global__ __launch_bounds__(NTH, 1) __cluster_dims__(2, 1, 1)
void cfc_main_kernel(
    const float* __restrict__ x,
    const float* __restrict__ b1_0, const float* __restrict__ b2_0,
    const float* __restrict__ b1_1, const float* __restrict__ b2_1,
    const float* __restrict__ b1_2, const float* __restrict__ b2_2,
    float* __restrict__ out, int write_h)
{
    extern __shared__ float sm[];
    float* xh0A  = sm + OFF_XH0;
    float* xh1A  = sm + OFF_XH1;
    float* xh2   = sm + OFF_XH2;
    float* part  = sm + OFF_PART;
    float* part2 = sm + OFF_PART2;
    float* sw2   = sm + OFF_SW2;

    const int tid = threadIdx.x;
    unsigned rank;
    asm("mov.u32 %0, %%cluster_ctarank;" : "=r"(rank));
    const unsigned peer = rank ^ 1u;
    const int b0  = (blockIdx.x >> 1) * ROWS;

    const int nj0 = rank ? 73 : 76;
    const int jb0 = rank ? 76 : 0;
    const int nj1 = rank ? 47 : 52;
    const int jb1 = rank ? 52 : 0;

    const unsigned sbase = smem_u32(sm);
    const unsigned a_fl0 = sbase + MB_FL0 * 4;
    const unsigned a_fl1 = sbase + MB_FL1 * 4;

    const int mat = tid / 160;
    const int rem = tid - mat * 160;
    const int jj  = rem;
    const int rsel = (mat == 0) ? 0 : mat;

    const int jg0 = rem % 20, kc0 = rem / 20;
    const int kb0 = kc0 * 35;
    const int jg1 = rem % 13, kc1 = rem / 13;
    const int kb1 = kc1 * 21;
    const bool act1 = (kc1 < 12);

    // ---- prologue ----
    for (int i = tid; i < 2 * XB0; i += NTH) xh0A[i] = 0.f;
    for (int i = tid; i < 2 * XB1; i += NTH) xh1A[i] = 0.f;
    for (int i = tid; i < 448;  i += NTH) xh2[i]  = 0.f;
    for (int i = tid; i < 3 * CAT2 * S2; i += NTH) sw2[i] = ((const float*)g_W2)[i];

    if (tid == 0) {
        mbar_init(a_fl0, 1);
        mbar_init(a_fl1, 1);
    }

    float rb1_0 = 0.f, rb2_0 = 0.f, rbc_0 = 0.f;
    float rb1_1 = 0.f, rb2_1 = 0.f, rbc_1 = 0.f;
    float rb1_2 = 0.f, rb2_2 = 0.f, rbc_2 = 0.f;
    if (jj < nj0) { rb1_0 = b1_0[jb0 + jj]; rb2_0 = b2_0[jb0 + jj]; rbc_0 = g_bc[jb0 + jj]; }
    if (jj < nj1) { rb1_1 = b1_1[jb1 + jj]; rb2_1 = b2_1[jb1 + jj]; rbc_1 = g_bc[NI + jb1 + jj]; }
    if (jj < NM)  { rb1_2 = b1_2[jj]; rb2_2 = b2_2[jj]; rbc_2 = g_bc[NI + NC + jj]; }

    // stage x_0 into buffer 0, prefetch x_1
    const int i0 = tid, i1 = tid + NTH;
    for (int i = tid; i < ROWS * IND; i += NTH) {
        int r = i >> 7, k = i & 127;
        float v = x[((size_t)(b0 + r) * TT + 0) * IND + k];
        *(unsigned long long*)&xh0A[k * 8 + r * 2] = pack2(v, v);
    }
    float xr0 = x[((size_t)(b0 + (i0 >> 7)) * TT + 1) * IND + (i0 & 127)];
    float xr1 = 0.f;
    if (i1 < ROWS * IND)
        xr1 = x[((size_t)(b0 + (i1 >> 7)) * TT + 1) * IND + (i1 & 127)];

    __syncthreads();
    asm volatile("barrier.cluster.arrive.aligned;" ::: "memory");
    asm volatile("barrier.cluster.wait.aligned;" ::: "memory");

    unsigned ph0 = 0, ph1 = 0;

    for (int t = 0; t < TT; ++t) {
        const int pr = (t & 1), pw = ((t + 1) & 1);
        float* xh0r = xh0A + pr * XB0;   // (a) reads: x_t + h0^{t-1}
        float* xh0w = xh0A + pw * XB0;   // (c) writes: h0^t ; restage x_{t+1}
        float* xh1r = xh1A + pr * XB1;   // (e) reads: h0^t + h1^{t-1}
        float* xh1w = xh1A + pw * XB1;   // (g) writes: h1^t

        // ============ (a) layer-0 partials ============
        {
            const ulonglong2* Wp =
                (const ulonglong2*)(g_W0[mat] + (size_t)kb0 * S0 + jb0 + jg0 * 4);
            const float* ab = xh0r + kb0 * 8;
            unsigned long long aA0 = 0, aB0 = 0, aA1 = 0, aB1 = 0;
            unsigned long long aA2 = 0, aB2 = 0, aA3 = 0, aB3 = 0;
            ulonglong2 wreg[5];
            #pragma unroll
            for (int i = 0; i < 5; ++i) wreg[i] = Wp[i * (S0 / 4)];
            Wp += 5 * (S0 / 4);
            #pragma unroll
            for (int b = 0; b < 7; ++b) {
                ulonglong2 wnxt[5];
                if (b + 1 < 7) {
                    #pragma unroll
                    for (int i = 0; i < 5; ++i) wnxt[i] = Wp[i * (S0 / 4)];
                    Wp += 5 * (S0 / 4);
                }
                #pragma unroll
                for (int i = 0; i < 5; ++i) {
                    ulonglong2 d01 = *(const ulonglong2*)(ab);
                    ulonglong2 d23 = *(const ulonglong2*)(ab + 4);
                    ab += 8;
                    aA0 = fma2(wreg[i].x, d01.x, aA0); aB0 = fma2(wreg[i].y, d01.x, aB0);
                    aA1 = fma2(wreg[i].x, d01.y, aA1); aB1 = fma2(wreg[i].y, d01.y, aB1);
                    aA2 = fma2(wreg[i].x, d23.x, aA2); aB2 = fma2(wreg[i].y, d23.x, aB2);
                    aA3 = fma2(wreg[i].x, d23.y, aA3); aB3 = fma2(wreg[i].y, d23.y, aB3);
                }
                if (b + 1 < 7) {
                    #pragma unroll
                    for (int i = 0; i < 5; ++i) wreg[i] = wnxt[i];
                }
            }
            float* P = part + (size_t)((kc0 * 3 + mat) * 4) * 80 + jg0 * 4;
            *(ulonglong2*)(P)       = make_ulonglong2(aA0, aB0);
            *(ulonglong2*)(P + 80)  = make_ulonglong2(aA1, aB1);
            *(ulonglong2*)(P + 160) = make_ulonglong2(aA2, aB2);
            *(ulonglong2*)(P + 240) = make_ulonglong2(aA3, aB3);
        }
        __syncthreads();

        // ============ (c) combine layer-0 + exchange + restage ============
        if (jj < nj0) {
            float a1 = 0.f, a2 = 0.f, ac = 0.f;
            #pragma unroll
            for (int c = 0; c < 8; ++c) {
                a1 += part[((c * 3 + 0) * 4 + rsel) * 80 + jj];
                a2 += part[((c * 3 + 1) * 4 + rsel) * 80 + jj];
                ac += part[((c * 3 + 2) * 4 + rsel) * 80 + jj];
            }
            float h = cfc_mix(a1, a2, ac, rb1_0, rb2_0, rbc_0);
            unsigned long long hh = pack2(h, h);
            const int jg = jb0 + jj;
            const int o0 = (IND + jg) * 8 + rsel * 2;
            const int o1 = jg * 8 + rsel * 2;
            *(unsigned long long*)&xh0w[o0] = hh;
            *(unsigned long long*)&xh1r[o1] = hh;
            st_peer_u64(sbase + (OFF_XH0 + pw * XB0 + o0) * 4, peer, hh);
            st_peer_u64(sbase + (OFF_XH1 + pr * XB1 + o1) * 4, peer, hh);
            if (mat == 0) {
                float c1 = 0.f, c2 = 0.f, cc = 0.f;
                #pragma unroll
                for (int c = 0; c < 8; ++c) {
                    c1 += part[((c * 3 + 0) * 4 + 3) * 80 + jj];
                    c2 += part[((c * 3 + 1) * 4 + 3) * 80 + jj];
                    cc += part[((c * 3 + 2) * 4 + 3) * 80 + jj];
                }
                float h3 = cfc_mix(c1, c2, cc, rb1_0, rb2_0, rbc_0);
                unsigned long long hh3 = pack2(h3, h3);
                *(unsigned long long*)&xh0w[o0 + 6] = hh3;   // rsel==0 here
                *(unsigned long long*)&xh1r[o1 + 6] = hh3;
                st_peer_u64(sbase + (OFF_XH0 + pw * XB0 + o0 + 6) * 4, peer, hh3);
                st_peer_u64(sbase + (OFF_XH1 + pr * XB1 + o1 + 6) * 4, peer, hh3);
            }
        }
        {   // restage x_{t+1} into write buffer, prefetch x_{t+2}
            *(unsigned long long*)&xh0w[(i0 & 127) * 8 + (i0 >> 7) * 2] = pack2(xr0, xr0);
            if (i1 < ROWS * IND)
                *(unsigned long long*)&xh0w[(i1 & 127) * 8 + (i1 >> 7) * 2] = pack2(xr1, xr1);
            int tn = t + 2; if (tn > TT - 1) tn = TT - 1;
            xr0 = x[((size_t)(b0 + (i0 >> 7)) * TT + tn) * IND + (i0 & 127)];
            if (i1 < ROWS * IND)
                xr1 = x[((size_t)(b0 + (i1 >> 7)) * TT + tn) * IND + (i1 & 127)];
        }
        __syncthreads();
        if (tid == 0) { fence_arrive_peer(a_fl0, peer); mbar_wait(a_fl0, ph0); }
        __syncthreads();
        ph0 ^= 1;

        // ============ (e) layer-1 partials (LDG streamed) ============
        if (act1) {
            const ulonglong2* Wp =
                (const ulonglong2*)(g_W1[mat] + (size_t)kb1 * S1 + jb1 + jg1 * 4);
            const float* ab = xh1r + kb1 * 8;
            unsigned long long aA0 = 0, aB0 = 0, aA1 = 0, aB1 = 0;
            unsigned long long aA2 = 0, aB2 = 0, aA3 = 0, aB3 = 0;
            ulonglong2 wreg[7];
            #pragma unroll
            for (int i = 0; i < 7; ++i) wreg[i] = Wp[i * (S1 / 4)];
            Wp += 7 * (S1 / 4);
            #pragma unroll
            for (int b = 0; b < 3; ++b) {
                ulonglong2 wnxt[7];
                if (b + 1 < 3) {
                    #pragma unroll
                    for (int i = 0; i < 7; ++i) wnxt[i] = Wp[i * (S1 / 4)];
                    Wp += 7 * (S1 / 4);
                }
                #pragma unroll
                for (int i = 0; i < 7; ++i) {
                    ulonglong2 d01 = *(const ulonglong2*)(ab);
                    ulonglong2 d23 = *(const ulonglong2*)(ab + 4);
                    ab += 8;
                    aA0 = fma2(wreg[i].x, d01.x, aA0); aB0 = fma2(wreg[i].y, d01.x, aB0);
                    aA1 = fma2(wreg[i].x, d01.y, aA1); aB1 = fma2(wreg[i].y, d01.y, aB1);
                    aA2 = fma2(wreg[i].x, d23.x, aA2); aB2 = fma2(wreg[i].y, d23.x, aB2);
                    aA3 = fma2(wreg[i].x, d23.y, aA3); aB3 = fma2(wreg[i].y, d23.y, aB3);
                }
                if (b + 1 < 3) {
                    #pragma unroll
                    for (int i = 0; i < 7; ++i) wreg[i] = wnxt[i];
                }
            }
            float* P = part + (size_t)((kc1 * 3 + mat) * 4) * 52 + jg1 * 4;
            *(ulonglong2*)(P)       = make_ulonglong2(aA0, aB0);
            *(ulonglong2*)(P + 52)  = make_ulonglong2(aA1, aB1);
            *(ulonglong2*)(P + 104) = make_ulonglong2(aA2, aB2);
            *(ulonglong2*)(P + 156) = make_ulonglong2(aA3, aB3);
        }
        __syncthreads();

        // ============ (g) combine layer-1 + exchange ============
        if (jj < nj1) {
            float a1 = 0.f, a2 = 0.f, ac = 0.f;
            #pragma unroll
            for (int c = 0; c < 12; ++c) {
                a1 += part[((c * 3 + 0) * 4 + rsel) * 52 + jj];
                a2 += part[((c * 3 + 1) * 4 + rsel) * 52 + jj];
                ac += part[((c * 3 + 2) * 4 + rsel) * 52 + jj];
            }
            float h = cfc_mix(a1, a2, ac, rb1_1, rb2_1, rbc_1);
            unsigned long long hh = pack2(h, h);
            const int jg = jb1 + jj;
            const int o1 = (NI + jg) * 8 + rsel * 2;
            const int o2 = jg * 4 + rsel;
            *(unsigned long long*)&xh1w[o1] = hh;
            xh2[o2] = h;
            st_peer_u64(sbase + (OFF_XH1 + pw * XB1 + o1) * 4, peer, hh);
            st_peer_u32(sbase + (OFF_XH2 + o2) * 4, peer, h);
            if (mat == 0) {
                float c1 = 0.f, c2 = 0.f, cc = 0.f;
                #pragma unroll
                for (int c = 0; c < 12; ++c) {
                    c1 += part[((c * 3 + 0) * 4 + 3) * 52 + jj];
                    c2 += part[((c * 3 + 1) * 4 + 3) * 52 + jj];
                    cc += part[((c * 3 + 2) * 4 + 3) * 52 + jj];
                }
                float h3 = cfc_mix(c1, c2, cc, rb1_1, rb2_1, rbc_1);
                unsigned long long hh3 = pack2(h3, h3);
                *(unsigned long long*)&xh1w[o1 + 6] = hh3;   // rsel==0 here
                xh2[jg * 4 + 3] = h3;
                st_peer_u64(sbase + (OFF_XH1 + pw * XB1 + o1 + 6) * 4, peer, hh3);
                st_peer_u32(sbase + (OFF_XH2 + jg * 4 + 3) * 4, peer, h3);
            }
        }
        __syncthreads();
        if (tid == 0) { fence_arrive_peer(a_fl1, peer); mbar_wait(a_fl1, ph1); }
        __syncthreads();
        ph1 ^= 1;

        // ============ (i) layer-2 partials ============
        {
            int j2 = jj & 7, kc2 = jj >> 3;
            int kb = kc2 * 6;
            int ke = kb + 6; if (ke > CAT2) ke = CAT2; if (kb > CAT2) kb = CAT2;
            unsigned long long p01 = 0, p23 = 0;
            const float* W = sw2 + mat * (CAT2 * S2) + j2;
            for (int k = kb; k < ke; ++k) {
                float w = W[k * 8];
                unsigned long long ww = pack2(w, w);
                ulonglong2 u = *(const ulonglong2*)&xh2[k * 4];
                p01 = fma2(ww, u.x, p01);
                p23 = fma2(ww, u.y, p23);
            }
            *(ulonglong2*)&part2[(mat * 160 + jj) * 4] = make_ulonglong2(p01, p23);
        }
        __syncthreads();

        // ============ (k) combine layer-2 (rank0 writes y) ============
        if (mat == 0 && jj < NM) {
            unsigned long long s0a = 0, s0b = 0, s1a = 0, s1b = 0, s2a = 0, s2b = 0;
            #pragma unroll 4
            for (int kc = 0; kc < 20; ++kc) {
                int p = (kc * 8 + jj) * 4;
                ulonglong2 u0 = *(const ulonglong2*)&part2[p];
                ulonglong2 u1 = *(const ulonglong2*)&part2[640 + p];
                ulonglong2 u2 = *(const ulonglong2*)&part2[1280 + p];
                s0a = add2(s0a, u0.x); s0b = add2(s0b, u0.y);
                s1a = add2(s1a, u1.x); s1b = add2(s1b, u1.y);
                s2a = add2(s2a, u2.x); s2b = add2(s2b, u2.y);
            }
            float a1[4], a2[4], ac[4];
            unpack2(s0a, a1[0], a1[1]); unpack2(s0b, a1[2], a1[3]);
            unpack2(s1a, a2[0], a2[1]); unpack2(s1b, a2[2], a2[3]);
            unpack2(s2a, ac[0], ac[1]); unpack2(s2b, ac[2], ac[3]);
            #pragma unroll
            for (int r = 0; r < 4; ++r) {
                float h = cfc_mix(a1[r], a2[r], ac[r], rb1_2, rb2_2, rbc_2);
                xh2[(NC + jj) * 4 + r] = h;
                if (rank == 0)
                    out[((size_t)(b0 + r) * TT + t) * NM + jj] = tanhf(h);
            }
        }
        // next conflicting access is several barriers away
    }

    __syncthreads();
    if (write_h && rank == 0) {
        // TT even: final h0 in xh0 buf0, final h1 in xh1 buf0
        size_t base = (size_t)BB * TT * NM;
        for (int pass = 0; pass < 2; ++pass) {
            int rr = (pass == 0) ? rsel : 3;
            if (pass == 1 && mat != 0) break;
            size_t ro = base + (size_t)(b0 + rr) * 256;
            if (jj < NI) out[ro + jj]           = xh0A[(IND + jj) * 8 + rr * 2];
            if (jj < NC) out[ro + NI + jj]      = xh1A[(NI + jj) * 8 + rr * 2];
            if (jj < NM) out[ro + NI + NC + jj] = xh2[(NC + jj) * 4 + rr];
        }
    }
    asm volatile("barrier.cluster.arrive.aligned;" ::: "memory");
    asm volatile("barrier.cluster.wait.aligned;" ::: "memory");
}

// ---------------------------------------------------------------------------
extern "C" void kernel_launch(void* const* d_in, const int* in_sizes, int n_in,
                              void* d_out, int out_size)
{
    const float *x, *dt;
    const float *w1[3], *b1[3], *w2[3], *b2[3], *wa[3], *ba[3], *wb[3], *bb[3];
    const int   *m[3];

    if (in_sizes[0] == BB * TT * IND) {
        x  = (const float*)d_in[0];
        dt = (const float*)d_in[1];
        for (int l = 0; l < 3; l++) {
            int base = 2 + 9 * l;
            w1[l] = (const float*)d_in[base + 0];
            b1[l] = (const float*)d_in[base + 1];
            w2[l] = (const float*)d_in[base + 2];
            b2[l] = (const float*)d_in[base + 3];
            wa[l] = (const float*)d_in[base + 4];
            ba[l] = (const float*)d_in[base + 5];
            wb[l] = (const float*)d_in[base + 6];
            bb[l] = (const float*)d_in[base + 7];
            m[l]  = (const int*)  d_in[base + 8];
        }
    } else {
        for (int l = 0; l < 3; l++) {
            int base = 9 * l;
            w1[l] = (const float*)d_in[base + 0];
            w2[l] = (const float*)d_in[base + 1];
            wa[l] = (const float*)d_in[base + 2];
            wb[l] = (const float*)d_in[base + 3];
            b1[l] = (const float*)d_in[base + 4];
            b2[l] = (const float*)d_in[base + 5];
            ba[l] = (const float*)d_in[base + 6];
            bb[l] = (const float*)d_in[base + 7];
            m[l]  = (const int*)  d_in[base + 8];
        }
        x  = (const float*)d_in[27];
        dt = (const float*)d_in[28];
    }

    cfc_precompute_kernel<<<148, 256>>>(
        w1[0], w2[0], wa[0], wb[0], ba[0], bb[0], m[0],
        w1[1], w2[1], wa[1], wb[1], ba[1], bb[1], m[1],
        w1[2], w2[2], wa[2], wb[2], ba[2], bb[2], m[2],
        dt);

    cudaFuncSetAttribute(cfc_main_kernel,
                         cudaFuncAttributeMaxDynamicSharedMemorySize, SMEM_BYTES);

    int write_h = (out_size >= BB * TT * NM + BB * 256) ? 1 : 0;
    cfc_main_kernel<<<(BB / ROWS) * 2, NTH, SMEM_BYTES>>>(
        x, b1[0], b2[0], b1[1], b2[1], b1[2], b2[2],
        (float*)d_out, write_h);
}

// round 10
// speedup vs baseline: 1.1555x; 1.1555x over previous
#include <cuda_runtime.h>
#include <math.h>

typedef unsigned long long ull;

// Problem constants
#define BB   256
#define TT   512
#define IND  128
#define NI   149
#define NCC  99
#define NM   8
#define CAT2 107
#define S0   160
#define S1   128
#define K0P  280          // 5 chunks x 56
#define K1P  252          // 4 chunks x 63
#define ROWS 4
#define NTH  480

// SMEM layout (float offsets)
#define XB0F  2240        // 280*8
#define XB1F  2016        // 252*8
#define XB2F  448         // 112*4
#define OFF_XH0   0
#define OFF_XH1   4480
#define OFF_XH2   8512
#define OFF_PARTA 9408    // 5*3*4*80 = 4800
#define OFF_PARTB 14208   // 4*3*4*56 = 2688
#define OFF_SW2   16896   // 3*107*8 = 2568
#define OFF_MBAR  19464   // 8 mbarriers = 16 floats
#define SMEM_FLOATS 19480
#define SMEM_BYTES  (SMEM_FLOATS * 4)

// mbarrier slots (float offsets from sm base): [iface][parity]
#define MB_RDYA(s)  (OFF_MBAR + 0 + 2*(s))
#define MB_CONB(s)  (OFF_MBAR + 4 + 2*(s))
#define MB_RDYB(s)  (OFF_MBAR + 8 + 2*(s))
#define MB_CONC(s)  (OFF_MBAR + 12 + 2*(s))

__device__ float g_W0[3][K0P * S0];
__device__ float g_W1[3][K1P * S1];
__device__ float g_W2[3][CAT2 * 8];
__device__ float g_bc[NI + NCC + NM];

// ---------------------------------------------------------------------------
__global__ void cfc_precompute_kernel(
    const float* __restrict__ w1_0, const float* __restrict__ w2_0,
    const float* __restrict__ wa_0, const float* __restrict__ wb_0,
    const float* __restrict__ ba_0, const float* __restrict__ bb_0,
    const int*   __restrict__ m0,
    const float* __restrict__ w1_1, const float* __restrict__ w2_1,
    const float* __restrict__ wa_1, const float* __restrict__ wb_1,
    const float* __restrict__ ba_1, const float* __restrict__ bb_1,
    const int*   __restrict__ m1,
    const float* __restrict__ w1_2, const float* __restrict__ w2_2,
    const float* __restrict__ wa_2, const float* __restrict__ wb_2,
    const float* __restrict__ ba_2, const float* __restrict__ bb_2,
    const int*   __restrict__ m2,
    const float* __restrict__ dt)
{
    const float ts = dt[0];
    const int idx    = blockIdx.x * blockDim.x + threadIdx.x;
    const int stride = gridDim.x * blockDim.x;

    for (int i = idx; i < K0P * S0; i += stride) {
        int k = i / S0, j = i - k * S0;
        float v1 = 0.f, v2 = 0.f, vc = 0.f;
        if (j < NI && k < (IND + NI)) {
            int src = j * (IND + NI) + k;
            float mm = (float)m0[src];
            v1 = w1_0[src] * mm;
            v2 = w2_0[src] * mm;
            vc = ts * wa_0[src] + wb_0[src];
        }
        g_W0[0][i] = v1; g_W0[1][i] = v2; g_W0[2][i] = vc;
    }
    for (int i = idx; i < K1P * S1; i += stride) {
        int k = i / S1, j = i - k * S1;
        float v1 = 0.f, v2 = 0.f, vc = 0.f;
        if (j < NCC && k < (NI + NCC)) {
            int src = j * (NI + NCC) + k;
            float mm = (float)m1[src];
            v1 = w1_1[src] * mm;
            v2 = w2_1[src] * mm;
            vc = ts * wa_1[src] + wb_1[src];
        }
        g_W1[0][i] = v1; g_W1[1][i] = v2; g_W1[2][i] = vc;
    }
    for (int i = idx; i < CAT2 * 8; i += stride) {
        int k = i / 8, j = i - k * 8;
        int src = j * CAT2 + k;
        float mm = (float)m2[src];
        g_W2[0][i] = w1_2[src] * mm;
        g_W2[1][i] = w2_2[src] * mm;
        g_W2[2][i] = ts * wa_2[src] + wb_2[src];
    }
    for (int j = idx; j < NI;  j += stride) g_bc[j]            = ts * ba_0[j] + bb_0[j];
    for (int j = idx; j < NCC; j += stride) g_bc[NI + j]       = ts * ba_1[j] + bb_1[j];
    for (int j = idx; j < NM;  j += stride) g_bc[NI + NCC + j] = ts * ba_2[j] + bb_2[j];
}

// ---------------------------------------------------------------------------
__device__ __forceinline__ ull pack2(float a, float b) {
    ull r; asm("mov.b64 %0, {%1, %2};" : "=l"(r) : "f"(a), "f"(b)); return r;
}
__device__ __forceinline__ void unpack2(ull v, float& a, float& b) {
    asm("mov.b64 {%0, %1}, %2;" : "=f"(a), "=f"(b) : "l"(v));
}
__device__ __forceinline__ ull fma2(ull a, ull b, ull c) {
    ull d; asm("fma.rn.f32x2 %0, %1, %2, %3;" : "=l"(d) : "l"(a), "l"(b), "l"(c)); return d;
}
__device__ __forceinline__ float sigmoidf_(float z) { return 1.0f / (1.0f + expf(-z)); }
__device__ __forceinline__ float cfc_mix(float a1, float a2, float ac,
                                         float b1, float b2, float bc) {
    float ff1 = tanhf(a1 + b1);
    float ff2 = tanhf(a2 + b2);
    float ti  = sigmoidf_(ac + bc);
    return ff1 + ti * (ff2 - ff1);
}
__device__ __forceinline__ unsigned smem_u32(const void* p) {
    unsigned a;
    asm("{ .reg .u64 t; cvta.to.shared.u64 t, %1; cvt.u32.u64 %0, t; }" : "=r"(a) : "l"(p));
    return a;
}
__device__ __forceinline__ void mbar_init(unsigned addr, unsigned count) {
    asm volatile("mbarrier.init.shared.b64 [%0], %1;" :: "r"(addr), "r"(count) : "memory");
}
__device__ __forceinline__ void mbar_wait(unsigned addr, unsigned parity) {
    unsigned done = 0;
    do {
        asm volatile(
            "{\n\t.reg .pred P;\n\t"
            "mbarrier.try_wait.parity.acquire.cluster.shared::cta.b64 P, [%1], %2, 0x989680;\n\t"
            "selp.b32 %0, 1, 0, P;\n\t}"
            : "=r"(done) : "r"(addr), "r"(parity) : "memory");
    } while (!done);
}
__device__ __forceinline__ void mbar_arrive_local(unsigned addr) {
    asm volatile("mbarrier.arrive.release.cluster.shared::cta.b64 _, [%0];"
                 :: "r"(addr) : "memory");
}
__device__ __forceinline__ void mbar_arrive_peer(unsigned addr, unsigned peer) {
    asm volatile(
        "{\n\t.reg .b32 ra;\n\t"
        "mapa.shared::cluster.u32 ra, %0, %1;\n\t"
        "mbarrier.arrive.release.cluster.shared::cluster.b64 _, [ra];\n\t}"
        :: "r"(addr), "r"(peer) : "memory");
}
__device__ __forceinline__ void cfence() {
    asm volatile("fence.acq_rel.cluster;" ::: "memory");
}
__device__ __forceinline__ void st_peer_u64(unsigned addr, unsigned peer, ull v) {
    asm volatile(
        "{\n\t.reg .b32 ra;\n\t"
        "mapa.shared::cluster.u32 ra, %0, %1;\n\t"
        "st.shared::cluster.u64 [ra], %2;\n\t}"
        :: "r"(addr), "r"(peer), "l"(v) : "memory");
}
__device__ __forceinline__ void st_peer_u32(unsigned addr, unsigned peer, float v) {
    asm volatile(
        "{\n\t.reg .b32 ra;\n\t"
        "mapa.shared::cluster.u32 ra, %0, %1;\n\t"
        "st.shared::cluster.f32 [ra], %2;\n\t}"
        :: "r"(addr), "r"(peer), "f"(v) : "memory");
}
#define BARN(id, n) asm volatile("bar.sync %0, %1;" :: "r"(id), "r"(n) : "memory")

// ---------------------------------------------------------------------------
// Pipelined kernel: 64 clusters x 2 CTAs; each cluster owns 4 batch rows with
// j split across the pair. Within a CTA, warps 0-8 = layer0 (stage A),
// warps 9-13 = layer1 (stage B), warp 14 = layer2 (stage C); stages run as a
// software pipeline (A at step t+1 overlaps B/C at step t).
// ---------------------------------------------------------------------------
__global__ __launch_bounds__(NTH, 1) __cluster_dims__(2, 1, 1)
void cfc_main_kernel(
    const float* __restrict__ x,
    const float* __restrict__ b1_0, const float* __restrict__ b2_0,
    const float* __restrict__ b1_1, const float* __restrict__ b2_1,
    const float* __restrict__ b1_2, const float* __restrict__ b2_2,
    float* __restrict__ out, int write_h)
{
    extern __shared__ float sm[];
    float* xh0A  = sm + OFF_XH0;
    float* xh1A  = sm + OFF_XH1;
    float* xh2A  = sm + OFF_XH2;
    float* partA = sm + OFF_PARTA;
    float* partB = sm + OFF_PARTB;
    float* sw2   = sm + OFF_SW2;

    const int tid = threadIdx.x;
    unsigned rank;
    asm("mov.u32 %0, %%cluster_ctarank;" : "=r"(rank));
    const unsigned peer = rank ^ 1u;
    const int b0 = (blockIdx.x >> 1) * ROWS;

    const int nj0 = rank ? 73 : 76;
    const int jb0 = rank ? 76 : 0;
    const int nj1 = rank ? 47 : 52;
    const int jb1 = rank ? 52 : 0;

    const unsigned sbase = smem_u32(sm);

    // roles
    const bool isA = (tid < 288);
    const bool isB = (tid >= 288 && tid < 448);
    const bool isC = (tid >= 448);

    // stage A decomposition: 57 combos (3 mat x 19 jg-of-4) x 5 kc(56)
    const int at = tid;
    const int comboA = at % 57, kcA = at / 57;
    const int matA = comboA / 19, jgA = comboA % 19;
    const bool actA = isA && (at < 285);
    const bool combA = isA && (at < 152);
    const int cjA = at >> 1, crA = (at & 1) * 2;

    // stage B decomposition: 39 combos (3 mat x 13 jg-of-4) x 4 kc(63)
    const int bt = tid - 288;
    const int comboB = bt % 39, kcB = bt / 39;
    const int matB = comboB / 13, jgB = comboB % 13;
    const bool actB = isB && (bt < 156);
    const bool combB = isB && (bt < 104);
    const int cjB = bt >> 1, crB = (bt & 1) * 2;

    // stage C: 24 active (3 mat x 8 j)
    const int ct = tid - 448;
    const int matC = ct >> 3, jC = ct & 7;
    const bool actC = isC && (ct < 24);

    // ---- prologue ----
    for (int i = tid; i < 2 * XB0F; i += NTH) xh0A[i] = 0.f;
    for (int i = tid; i < 2 * XB1F; i += NTH) xh1A[i] = 0.f;
    for (int i = tid; i < 2 * XB2F; i += NTH) xh2A[i] = 0.f;
    for (int i = tid; i < 3 * CAT2 * 8; i += NTH) sw2[i] = ((const float*)g_W2)[i];
    if (tid == 0) {
        for (int s = 0; s < 2; ++s) {
            mbar_init(sbase + MB_RDYA(s) * 4, 2);
            mbar_init(sbase + MB_CONB(s) * 4, 2);
            mbar_init(sbase + MB_RDYB(s) * 4, 2);
            mbar_init(sbase + MB_CONC(s) * 4, 2);
        }
    }

    // biases per role
    float bA1 = 0.f, bA2 = 0.f, bAc = 0.f;
    if (combA && cjA < nj0) { bA1 = b1_0[jb0 + cjA]; bA2 = b2_0[jb0 + cjA]; bAc = g_bc[jb0 + cjA]; }
    float bB1 = 0.f, bB2 = 0.f, bBc = 0.f;
    if (combB && cjB < nj1) { bB1 = b1_1[jb1 + cjB]; bB2 = b2_1[jb1 + cjB]; bBc = g_bc[NI + jb1 + cjB]; }
    float bC1 = 0.f, bC2 = 0.f, bCc = 0.f;
    if (isC) { bC1 = b1_2[jC]; bC2 = b2_2[jC]; bCc = g_bc[NI + NCC + jC]; }

    // stage x_0 into xh0 buf0 (dup pairs), A prefetches x_1
    for (int i = tid; i < ROWS * IND; i += NTH) {
        int r = i >> 7, k = i & 127;
        float v = x[((size_t)(b0 + r) * TT + 0) * IND + k];
        *(ull*)&xh0A[k * 8 + r * 2] = pack2(v, v);
    }
    float xr0 = 0.f, xr1 = 0.f;
    const int i0 = tid, i1 = tid + 288;
    if (isA) {
        xr0 = x[((size_t)(b0 + (i0 >> 7)) * TT + 1) * IND + (i0 & 127)];
        if (i1 < ROWS * IND)
            xr1 = x[((size_t)(b0 + (i1 >> 7)) * TT + 1) * IND + (i1 & 127)];
    }

    __syncthreads();
    asm volatile("barrier.cluster.arrive.aligned;" ::: "memory");
    asm volatile("barrier.cluster.wait.aligned;" ::: "memory");

    if (isA) {
        // =================== STAGE A : layer 0 ===================
        for (int t = 0; t < TT; ++t) {
            const int pr = t & 1, pw = (t + 1) & 1;
            float* xh0r = xh0A + pr * XB0F;
            float* xh0w = xh0A + pw * XB0F;
            float* xh1c = xh1A + pr * XB1F;   // B(t)'s read buffer

            if (t >= 1)
                mbar_wait(sbase + MB_RDYA((t - 1) & 1) * 4, ((t - 1) >> 1) & 1);

            // (a) partials
            if (actA) {
                const ulonglong2* Wp = (const ulonglong2*)
                    (g_W0[matA] + (size_t)(kcA * 56) * S0 + jb0 + jgA * 4);
                const float* ab = xh0r + (kcA * 56) * 8;
                ull aA0 = 0, aB0 = 0, aA1 = 0, aB1 = 0;
                ull aA2 = 0, aB2 = 0, aA3 = 0, aB3 = 0;
                #pragma unroll 8
                for (int k = 0; k < 56; ++k) {
                    ulonglong2 w   = Wp[k * (S0 / 4)];
                    ulonglong2 d01 = *(const ulonglong2*)(ab + k * 8);
                    ulonglong2 d23 = *(const ulonglong2*)(ab + k * 8 + 4);
                    aA0 = fma2(w.x, d01.x, aA0); aB0 = fma2(w.y, d01.x, aB0);
                    aA1 = fma2(w.x, d01.y, aA1); aB1 = fma2(w.y, d01.y, aB1);
                    aA2 = fma2(w.x, d23.x, aA2); aB2 = fma2(w.y, d23.x, aB2);
                    aA3 = fma2(w.x, d23.y, aA3); aB3 = fma2(w.y, d23.y, aB3);
                }
                float* P = partA + (size_t)((kcA * 3 + matA) * 4) * 80 + jgA * 4;
                *(ulonglong2*)(P)       = make_ulonglong2(aA0, aB0);
                *(ulonglong2*)(P + 80)  = make_ulonglong2(aA1, aB1);
                *(ulonglong2*)(P + 160) = make_ulonglong2(aA2, aB2);
                *(ulonglong2*)(P + 240) = make_ulonglong2(aA3, aB3);
            }
            BARN(1, 288);

            if (t >= 2)
                mbar_wait(sbase + MB_CONB(t & 1) * 4, ((t - 2) >> 1) & 1);

            // (c) combine + exchange
            if (combA && cjA < nj0) {
                const int r0 = crA, r1 = crA + 1;
                float a1r0 = 0, a1r1 = 0, a2r0 = 0, a2r1 = 0, acr0 = 0, acr1 = 0;
                #pragma unroll
                for (int c = 0; c < 5; ++c) {
                    const float* P = partA + (size_t)(c * 12) * 80;
                    a1r0 += P[(0 * 4 + r0) * 80 + cjA];
                    a1r1 += P[(0 * 4 + r1) * 80 + cjA];
                    a2r0 += P[(1 * 4 + r0) * 80 + cjA];
                    a2r1 += P[(1 * 4 + r1) * 80 + cjA];
                    acr0 += P[(2 * 4 + r0) * 80 + cjA];
                    acr1 += P[(2 * 4 + r1) * 80 + cjA];
                }
                float h0v = cfc_mix(a1r0, a2r0, acr0, bA1, bA2, bAc);
                float h1v = cfc_mix(a1r1, a2r1, acr1, bA1, bA2, bAc);
                ull u0 = pack2(h0v, h0v), u1 = pack2(h1v, h1v);
                const int jg = jb0 + cjA;
                const int oX = (IND + jg) * 8;
                const int oH = jg * 8;
                *(ull*)&xh0w[oX + r0 * 2] = u0;
                *(ull*)&xh0w[oX + r1 * 2] = u1;
                *(ull*)&xh1c[oH + r0 * 2] = u0;
                *(ull*)&xh1c[oH + r1 * 2] = u1;
                st_peer_u64(sbase + (OFF_XH0 + pw * XB0F + oX + r0 * 2) * 4, peer, u0);
                st_peer_u64(sbase + (OFF_XH0 + pw * XB0F + oX + r1 * 2) * 4, peer, u1);
                st_peer_u64(sbase + (OFF_XH1 + pr * XB1F + oH + r0 * 2) * 4, peer, u0);
                st_peer_u64(sbase + (OFF_XH1 + pr * XB1F + oH + r1 * 2) * 4, peer, u1);
            }
            // x restage + prefetch
            *(ull*)&xh0w[(i0 & 127) * 8 + (i0 >> 7) * 2] = pack2(xr0, xr0);
            if (i1 < ROWS * IND)
                *(ull*)&xh0w[(i1 & 127) * 8 + (i1 >> 7) * 2] = pack2(xr1, xr1);
            {
                int tn = t + 2; if (tn > TT - 1) tn = TT - 1;
                xr0 = x[((size_t)(b0 + (i0 >> 7)) * TT + tn) * IND + (i0 & 127)];
                if (i1 < ROWS * IND)
                    xr1 = x[((size_t)(b0 + (i1 >> 7)) * TT + tn) * IND + (i1 & 127)];
            }
            BARN(1, 288);
            if (tid == 0) {
                cfence();
                mbar_arrive_local(sbase + MB_RDYA(t & 1) * 4);
                mbar_arrive_peer(sbase + MB_RDYA(t & 1) * 4, peer);
            }
        }
    } else if (isB) {
        // =================== STAGE B : layer 1 ===================
        for (int t = 0; t < TT; ++t) {
            const int pr = t & 1, pw = (t + 1) & 1;
            float* xh1r = xh1A + pr * XB1F;
            float* xh1w = xh1A + pw * XB1F;
            float* xh2c = xh2A + pr * XB2F;   // C(t)'s read buffer

            mbar_wait(sbase + MB_RDYA(t & 1) * 4, (t >> 1) & 1);
            if (t >= 1)
                mbar_wait(sbase + MB_RDYB((t - 1) & 1) * 4, ((t - 1) >> 1) & 1);

            // (e) partials
            if (actB) {
                const ulonglong2* Wp = (const ulonglong2*)
                    (g_W1[matB] + (size_t)(kcB * 63) * S1 + jb1 + jgB * 4);
                const float* ab = xh1r + (kcB * 63) * 8;
                ull aA0 = 0, aB0 = 0, aA1 = 0, aB1 = 0;
                ull aA2 = 0, aB2 = 0, aA3 = 0, aB3 = 0;
                #pragma unroll 7
                for (int k = 0; k < 63; ++k) {
                    ulonglong2 w   = Wp[k * (S1 / 4)];
                    ulonglong2 d01 = *(const ulonglong2*)(ab + k * 8);
                    ulonglong2 d23 = *(const ulonglong2*)(ab + k * 8 + 4);
                    aA0 = fma2(w.x, d01.x, aA0); aB0 = fma2(w.y, d01.x, aB0);
                    aA1 = fma2(w.x, d01.y, aA1); aB1 = fma2(w.y, d01.y, aB1);
                    aA2 = fma2(w.x, d23.x, aA2); aB2 = fma2(w.y, d23.x, aB2);
                    aA3 = fma2(w.x, d23.y, aA3); aB3 = fma2(w.y, d23.y, aB3);
                }
                float* P = partB + (size_t)((kcB * 3 + matB) * 4) * 56 + jgB * 4;
                *(ulonglong2*)(P)       = make_ulonglong2(aA0, aB0);
                *(ulonglong2*)(P + 56)  = make_ulonglong2(aA1, aB1);
                *(ulonglong2*)(P + 112) = make_ulonglong2(aA2, aB2);
                *(ulonglong2*)(P + 168) = make_ulonglong2(aA3, aB3);
            }
            BARN(2, 160);
            if (bt == 0) {   // done reading xh1 buf[t&1]
                mbar_arrive_local(sbase + MB_CONB(t & 1) * 4);
                mbar_arrive_peer(sbase + MB_CONB(t & 1) * 4, peer);
            }
            if (t >= 2)
                mbar_wait(sbase + MB_CONC(t & 1) * 4, ((t - 2) >> 1) & 1);

            // (g) combine + exchange
            if (combB && cjB < nj1) {
                const int r0 = crB, r1 = crB + 1;
                float a1r0 = 0, a1r1 = 0, a2r0 = 0, a2r1 = 0, acr0 = 0, acr1 = 0;
                #pragma unroll
                for (int c = 0; c < 4; ++c) {
                    const float* P = partB + (size_t)(c * 12) * 56;
                    a1r0 += P[(0 * 4 + r0) * 56 + cjB];
                    a1r1 += P[(0 * 4 + r1) * 56 + cjB];
                    a2r0 += P[(1 * 4 + r0) * 56 + cjB];
                    a2r1 += P[(1 * 4 + r1) * 56 + cjB];
                    acr0 += P[(2 * 4 + r0) * 56 + cjB];
                    acr1 += P[(2 * 4 + r1) * 56 + cjB];
                }
                float h0v = cfc_mix(a1r0, a2r0, acr0, bB1, bB2, bBc);
                float h1v = cfc_mix(a1r1, a2r1, acr1, bB1, bB2, bBc);
                ull u0 = pack2(h0v, h0v), u1 = pack2(h1v, h1v);
                const int jg = jb1 + cjB;
                const int oH = (NI + jg) * 8;
                const int o2 = jg * 4;
                *(ull*)&xh1w[oH + r0 * 2] = u0;
                *(ull*)&xh1w[oH + r1 * 2] = u1;
                xh2c[o2 + r0] = h0v;
                xh2c[o2 + r1] = h1v;
                st_peer_u64(sbase + (OFF_XH1 + pw * XB1F + oH + r0 * 2) * 4, peer, u0);
                st_peer_u64(sbase + (OFF_XH1 + pw * XB1F + oH + r1 * 2) * 4, peer, u1);
                st_peer_u32(sbase + (OFF_XH2 + pr * XB2F + o2 + r0) * 4, peer, h0v);
                st_peer_u32(sbase + (OFF_XH2 + pr * XB2F + o2 + r1) * 4, peer, h1v);
            }
            BARN(2, 160);
            if (bt == 0) {
                cfence();
                mbar_arrive_local(sbase + MB_RDYB(t & 1) * 4);
                mbar_arrive_peer(sbase + MB_RDYB(t & 1) * 4, peer);
            }
        }
    } else {
        // =================== STAGE C : layer 2 ===================
        for (int t = 0; t < TT; ++t) {
            const int pr = t & 1, pw = (t + 1) & 1;
            float* xh2r = xh2A + pr * XB2F;
            float* xh2w = xh2A + pw * XB2F;

            mbar_wait(sbase + MB_RDYB(t & 1) * 4, (t >> 1) & 1);

            ull acc01 = 0, acc23 = 0;
            if (actC) {
                const float* W = sw2 + matC * (CAT2 * 8) + jC;
                #pragma unroll 4
                for (int k = 0; k < CAT2; ++k) {
                    float w = W[k * 8];
                    ull ww = pack2(w, w);
                    ulonglong2 u = *(const ulonglong2*)(xh2r + k * 4);
                    acc01 = fma2(ww, u.x, acc01);
                    acc23 = fma2(ww, u.y, acc23);
                }
            }
            __syncwarp();
            if (ct == 0) {   // done reading xh2 buf[t&1]
                mbar_arrive_local(sbase + MB_CONC(t & 1) * 4);
                mbar_arrive_peer(sbase + MB_CONC(t & 1) * 4, peer);
            }
            ull m1_01 = __shfl_sync(0xffffffffu, acc01, 8 + jC);
            ull m1_23 = __shfl_sync(0xffffffffu, acc23, 8 + jC);
            ull m2_01 = __shfl_sync(0xffffffffu, acc01, 16 + jC);
            ull m2_23 = __shfl_sync(0xffffffffu, acc23, 16 + jC);
            if (ct < 8) {
                float a1[4], a2[4], ac[4];
                unpack2(acc01, a1[0], a1[1]); unpack2(acc23, a1[2], a1[3]);
                unpack2(m1_01, a2[0], a2[1]); unpack2(m1_23, a2[2], a2[3]);
                unpack2(m2_01, ac[0], ac[1]); unpack2(m2_23, ac[2], ac[3]);
                #pragma unroll
                for (int r = 0; r < 4; ++r) {
                    float h = cfc_mix(a1[r], a2[r], ac[r], bC1, bC2, bCc);
                    xh2w[(NCC + jC) * 4 + r] = h;
                    if (rank == 0)
                        out[((size_t)(b0 + r) * TT + t) * NM + jC] = tanhf(h);
                }
            }
            __syncwarp();
        }
    }

    __syncthreads();
    asm volatile("barrier.cluster.arrive.aligned;" ::: "memory");
    asm volatile("barrier.cluster.wait.aligned;" ::: "memory");
    cfence();

    if (write_h && rank == 0) {
        size_t base = (size_t)BB * TT * NM;
        for (int jt = tid; jt < 256; jt += NTH) {
            #pragma unroll
            for (int r = 0; r < 4; ++r) {
                float v;
                if (jt < NI)            v = xh0A[(IND + jt) * 8 + r * 2];
                else if (jt < NI + NCC) v = xh1A[(NI + (jt - NI)) * 8 + r * 2];
                else                    v = xh2A[(NCC + (jt - NI - NCC)) * 4 + r];
                out[base + (size_t)(b0 + r) * 256 + jt] = v;
            }
        }
    }
    asm volatile("barrier.cluster.arrive.aligned;" ::: "memory");
    asm volatile("barrier.cluster.wait.aligned;" ::: "memory");
}

// ---------------------------------------------------------------------------
extern "C" void kernel_launch(void* const* d_in, const int* in_sizes, int n_in,
                              void* d_out, int out_size)
{
    const float *x, *dt;
    const float *w1[3], *b1[3], *w2[3], *b2[3], *wa[3], *ba[3], *wb[3], *bb[3];
    const int   *m[3];

    if (in_sizes[0] == BB * TT * IND) {
        x  = (const float*)d_in[0];
        dt = (const float*)d_in[1];
        for (int l = 0; l < 3; l++) {
            int base = 2 + 9 * l;
            w1[l] = (const float*)d_in[base + 0];
            b1[l] = (const float*)d_in[base + 1];
            w2[l] = (const float*)d_in[base + 2];
            b2[l] = (const float*)d_in[base + 3];
            wa[l] = (const float*)d_in[base + 4];
            ba[l] = (const float*)d_in[base + 5];
            wb[l] = (const float*)d_in[base + 6];
            bb[l] = (const float*)d_in[base + 7];
            m[l]  = (const int*)  d_in[base + 8];
        }
    } else {
        for (int l = 0; l < 3; l++) {
            int base = 9 * l;
            w1[l] = (const float*)d_in[base + 0];
            w2[l] = (const float*)d_in[base + 1];
            wa[l] = (const float*)d_in[base + 2];
            wb[l] = (const float*)d_in[base + 3];
            b1[l] = (const float*)d_in[base + 4];
            b2[l] = (const float*)d_in[base + 5];
            ba[l] = (const float*)d_in[base + 6];
            bb[l] = (const float*)d_in[base + 7];
            m[l]  = (const int*)  d_in[base + 8];
        }
        x  = (const float*)d_in[27];
        dt = (const float*)d_in[28];
    }

    cfc_precompute_kernel<<<148, 256>>>(
        w1[0], w2[0], wa[0], wb[0], ba[0], bb[0], m[0],
        w1[1], w2[1], wa[1], wb[1], ba[1], bb[1], m[1],
        w1[2], w2[2], wa[2], wb[2], ba[2], bb[2], m[2],
        dt);

    cudaFuncSetAttribute(cfc_main_kernel,
                         cudaFuncAttributeMaxDynamicSharedMemorySize, SMEM_BYTES);

    int write_h = (out_size >= BB * TT * NM + BB * 256) ? 1 : 0;
    cfc_main_kernel<<<(BB / ROWS) * 2, NTH, SMEM_BYTES>>>(
        x, b1[0], b2[0], b1[1], b2[1], b1[2], b2[2],
        (float*)d_out, write_h);
}

// round 11
// speedup vs baseline: 1.1889x; 1.0289x over previous
#include <cuda_runtime.h>
#include <math.h>

typedef unsigned long long ull;

// Problem constants
#define BB   256
#define TT   512
#define IND  128
#define NI   149
#define NCC  99
#define NM   8
#define CAT0 277
#define CAT1 248
#define CAT2 107
#define K0P  280          // 5 chunks x 56
#define K1P  252          // 4 chunks x 63
#define ROWS 4
#define NTH  480
#define RS0  240          // fused row stride layer0 (3*76=228 active)
#define RS1  160          // fused row stride layer1 (3*52=156 active)

// SMEM layout (float offsets)
#define XB0F  2240        // 280*8
#define XB1F  2016        // 252*8
#define XB2F  448         // 112*4
#define OFF_XH0   0
#define OFF_XH1   4480
#define OFF_XH2   8512
#define OFF_PARTA 9408    // 5*3*4*80 = 4800
#define OFF_PARTB 14208   // 4*3*4*56 = 2688
#define OFF_SW2   16896   // 3*107*8 = 2568
#define OFF_MBAR  19464   // 8 mbarriers = 16 floats
#define SMEM_FLOATS 19480
#define SMEM_BYTES  (SMEM_FLOATS * 4)

#define MB_RDYA(s)  (OFF_MBAR + 0 + 2*(s))
#define MB_CONB(s)  (OFF_MBAR + 4 + 2*(s))
#define MB_RDYB(s)  (OFF_MBAR + 8 + 2*(s))
#define MB_CONC(s)  (OFF_MBAR + 12 + 2*(s))

// Fused per-rank weight arrays: one k-row = [mat0 j0..75 | mat1 ... | mat2 ...]
// so warp-consecutive combos load contiguous bytes.
__device__ float g_W0f[2][K0P * RS0];
__device__ float g_W1f[2][K1P * RS1];
__device__ float g_W2[3][CAT2 * 8];
__device__ float g_bc[NI + NCC + NM];

// ---------------------------------------------------------------------------
__global__ void cfc_precompute_kernel(
    const float* __restrict__ w1_0, const float* __restrict__ w2_0,
    const float* __restrict__ wa_0, const float* __restrict__ wb_0,
    const float* __restrict__ ba_0, const float* __restrict__ bb_0,
    const int*   __restrict__ m0,
    const float* __restrict__ w1_1, const float* __restrict__ w2_1,
    const float* __restrict__ wa_1, const float* __restrict__ wb_1,
    const float* __restrict__ ba_1, const float* __restrict__ bb_1,
    const int*   __restrict__ m1,
    const float* __restrict__ w1_2, const float* __restrict__ w2_2,
    const float* __restrict__ wa_2, const float* __restrict__ wb_2,
    const float* __restrict__ ba_2, const float* __restrict__ bb_2,
    const int*   __restrict__ m2,
    const float* __restrict__ dt)
{
    const float ts = dt[0];
    const int idx    = blockIdx.x * blockDim.x + threadIdx.x;
    const int stride = gridDim.x * blockDim.x;

    // layer-0 fused: rank r, row k, col c: c<228 -> mat=c/76, jl=c%76
    for (int i = idx; i < 2 * K0P * RS0; i += stride) {
        int r = i / (K0P * RS0), rem = i - r * (K0P * RS0);
        int k = rem / RS0, c = rem - k * RS0;
        float v = 0.f;
        if (c < 228 && k < CAT0) {
            int mat = c / 76, jl = c - mat * 76;
            int jb = r ? 76 : 0, nj = r ? 73 : 76;
            if (jl < nj) {
                int j = jb + jl;
                int src = j * CAT0 + k;
                float mm = (float)m0[src];
                if (mat == 0)      v = w1_0[src] * mm;
                else if (mat == 1) v = w2_0[src] * mm;
                else               v = ts * wa_0[src] + wb_0[src];
            }
        }
        g_W0f[r][k * RS0 + c] = v;
    }
    // layer-1 fused: c<156 -> mat=c/52, jl=c%52
    for (int i = idx; i < 2 * K1P * RS1; i += stride) {
        int r = i / (K1P * RS1), rem = i - r * (K1P * RS1);
        int k = rem / RS1, c = rem - k * RS1;
        float v = 0.f;
        if (c < 156 && k < CAT1) {
            int mat = c / 52, jl = c - mat * 52;
            int jb = r ? 52 : 0, nj = r ? 47 : 52;
            if (jl < nj) {
                int j = jb + jl;
                int src = j * CAT1 + k;
                float mm = (float)m1[src];
                if (mat == 0)      v = w1_1[src] * mm;
                else if (mat == 1) v = w2_1[src] * mm;
                else               v = ts * wa_1[src] + wb_1[src];
            }
        }
        g_W1f[r][k * RS1 + c] = v;
    }
    for (int i = idx; i < CAT2 * 8; i += stride) {
        int k = i / 8, j = i - k * 8;
        int src = j * CAT2 + k;
        float mm = (float)m2[src];
        g_W2[0][i] = w1_2[src] * mm;
        g_W2[1][i] = w2_2[src] * mm;
        g_W2[2][i] = ts * wa_2[src] + wb_2[src];
    }
    for (int j = idx; j < NI;  j += stride) g_bc[j]            = ts * ba_0[j] + bb_0[j];
    for (int j = idx; j < NCC; j += stride) g_bc[NI + j]       = ts * ba_1[j] + bb_1[j];
    for (int j = idx; j < NM;  j += stride) g_bc[NI + NCC + j] = ts * ba_2[j] + bb_2[j];
}

// ---------------------------------------------------------------------------
__device__ __forceinline__ ull pack2(float a, float b) {
    ull r; asm("mov.b64 %0, {%1, %2};" : "=l"(r) : "f"(a), "f"(b)); return r;
}
__device__ __forceinline__ void unpack2(ull v, float& a, float& b) {
    asm("mov.b64 {%0, %1}, %2;" : "=f"(a), "=f"(b) : "l"(v));
}
__device__ __forceinline__ ull fma2(ull a, ull b, ull c) {
    ull d; asm("fma.rn.f32x2 %0, %1, %2, %3;" : "=l"(d) : "l"(a), "l"(b), "l"(c)); return d;
}
__device__ __forceinline__ float sigmoidf_(float z) { return 1.0f / (1.0f + expf(-z)); }
__device__ __forceinline__ float cfc_mix(float a1, float a2, float ac,
                                         float b1, float b2, float bc) {
    float ff1 = tanhf(a1 + b1);
    float ff2 = tanhf(a2 + b2);
    float ti  = sigmoidf_(ac + bc);
    return ff1 + ti * (ff2 - ff1);
}
__device__ __forceinline__ unsigned smem_u32(const void* p) {
    unsigned a;
    asm("{ .reg .u64 t; cvta.to.shared.u64 t, %1; cvt.u32.u64 %0, t; }" : "=r"(a) : "l"(p));
    return a;
}
__device__ __forceinline__ void mbar_init(unsigned addr, unsigned count) {
    asm volatile("mbarrier.init.shared.b64 [%0], %1;" :: "r"(addr), "r"(count) : "memory");
}
__device__ __forceinline__ void mbar_wait(unsigned addr, unsigned parity) {
    unsigned done = 0;
    do {
        asm volatile(
            "{\n\t.reg .pred P;\n\t"
            "mbarrier.try_wait.parity.acquire.cluster.shared::cta.b64 P, [%1], %2, 0x989680;\n\t"
            "selp.b32 %0, 1, 0, P;\n\t}"
            : "=r"(done) : "r"(addr), "r"(parity) : "memory");
    } while (!done);
}
__device__ __forceinline__ void mbar_arrive_local(unsigned addr) {
    asm volatile("mbarrier.arrive.release.cluster.shared::cta.b64 _, [%0];"
                 :: "r"(addr) : "memory");
}
__device__ __forceinline__ void mbar_arrive_peer(unsigned addr, unsigned peer) {
    asm volatile(
        "{\n\t.reg .b32 ra;\n\t"
        "mapa.shared::cluster.u32 ra, %0, %1;\n\t"
        "mbarrier.arrive.release.cluster.shared::cluster.b64 _, [ra];\n\t}"
        :: "r"(addr), "r"(peer) : "memory");
}
__device__ __forceinline__ void cfence() {
    asm volatile("fence.acq_rel.cluster;" ::: "memory");
}
__device__ __forceinline__ void st_peer_u64(unsigned addr, unsigned peer, ull v) {
    asm volatile(
        "{\n\t.reg .b32 ra;\n\t"
        "mapa.shared::cluster.u32 ra, %0, %1;\n\t"
        "st.shared::cluster.u64 [ra], %2;\n\t}"
        :: "r"(addr), "r"(peer), "l"(v) : "memory");
}
__device__ __forceinline__ void st_peer_u32(unsigned addr, unsigned peer, float v) {
    asm volatile(
        "{\n\t.reg .b32 ra;\n\t"
        "mapa.shared::cluster.u32 ra, %0, %1;\n\t"
        "st.shared::cluster.f32 [ra], %2;\n\t}"
        :: "r"(addr), "r"(peer), "f"(v) : "memory");
}
#define BARN(id, n) asm volatile("bar.sync %0, %1;" :: "r"(id), "r"(n) : "memory")

// ---------------------------------------------------------------------------
// Pipelined kernel (R10 structure): 64 clusters x 2 CTAs, 4 rows/cluster,
// j split across pair; warps 0-8 = layer0 (A), 9-13 = layer1 (B),
// warp 14 = layer2 (C). Fused contiguous weight rows for coalesced LDG.
// ---------------------------------------------------------------------------
__global__ __launch_bounds__(NTH, 1) __cluster_dims__(2, 1, 1)
void cfc_main_kernel(
    const float* __restrict__ x,
    const float* __restrict__ b1_0, const float* __restrict__ b2_0,
    const float* __restrict__ b1_1, const float* __restrict__ b2_1,
    const float* __restrict__ b1_2, const float* __restrict__ b2_2,
    float* __restrict__ out, int write_h)
{
    extern __shared__ float sm[];
    float* xh0A  = sm + OFF_XH0;
    float* xh1A  = sm + OFF_XH1;
    float* xh2A  = sm + OFF_XH2;
    float* partA = sm + OFF_PARTA;
    float* partB = sm + OFF_PARTB;
    float* sw2   = sm + OFF_SW2;

    const int tid = threadIdx.x;
    unsigned rank;
    asm("mov.u32 %0, %%cluster_ctarank;" : "=r"(rank));
    const unsigned peer = rank ^ 1u;
    const int b0 = (blockIdx.x >> 1) * ROWS;

    const int nj0 = rank ? 73 : 76;
    const int jb0 = rank ? 76 : 0;
    const int nj1 = rank ? 47 : 52;
    const int jb1 = rank ? 52 : 0;

    const unsigned sbase = smem_u32(sm);

    const bool isA = (tid < 288);
    const bool isB = (tid >= 288 && tid < 448);
    const bool isC = (tid >= 448);

    // stage A: 57 combos (mat*19+jg) x 5 kc(56)
    const int at = tid;
    const int comboA = at % 57, kcA = at / 57;
    const int matA = comboA / 19, jgA = comboA % 19;
    const bool actA = isA && (at < 285);
    const bool combA = isA && (at < 152);
    const int cjA = at >> 1, crA = (at & 1) * 2;

    // stage B: 39 combos (mat*13+jg) x 4 kc(63)
    const int bt = tid - 288;
    const int comboB = bt % 39, kcB = bt / 39;
    const int matB = comboB / 13, jgB = comboB % 13;
    const bool actB = isB && (bt < 156);
    const bool combB = isB && (bt < 104);
    const int cjB = bt >> 1, crB = (bt & 1) * 2;

    // stage C
    const int ct = tid - 448;
    const int matC = ct >> 3, jC = ct & 7;
    const bool actC = isC && (ct < 24);

    // ---- prologue ----
    for (int i = tid; i < 2 * XB0F; i += NTH) xh0A[i] = 0.f;
    for (int i = tid; i < 2 * XB1F; i += NTH) xh1A[i] = 0.f;
    for (int i = tid; i < 2 * XB2F; i += NTH) xh2A[i] = 0.f;
    for (int i = tid; i < 3 * CAT2 * 8; i += NTH) sw2[i] = ((const float*)g_W2)[i];
    if (tid == 0) {
        for (int s = 0; s < 2; ++s) {
            mbar_init(sbase + MB_RDYA(s) * 4, 2);
            mbar_init(sbase + MB_CONB(s) * 4, 2);
            mbar_init(sbase + MB_RDYB(s) * 4, 2);
            mbar_init(sbase + MB_CONC(s) * 4, 2);
        }
    }

    float bA1 = 0.f, bA2 = 0.f, bAc = 0.f;
    if (combA && cjA < nj0) { bA1 = b1_0[jb0 + cjA]; bA2 = b2_0[jb0 + cjA]; bAc = g_bc[jb0 + cjA]; }
    float bB1 = 0.f, bB2 = 0.f, bBc = 0.f;
    if (combB && cjB < nj1) { bB1 = b1_1[jb1 + cjB]; bB2 = b2_1[jb1 + cjB]; bBc = g_bc[NI + jb1 + cjB]; }
    float bC1 = 0.f, bC2 = 0.f, bCc = 0.f;
    if (isC) { bC1 = b1_2[jC]; bC2 = b2_2[jC]; bCc = g_bc[NI + NCC + jC]; }

    for (int i = tid; i < ROWS * IND; i += NTH) {
        int r = i >> 7, k = i & 127;
        float v = x[((size_t)(b0 + r) * TT + 0) * IND + k];
        *(ull*)&xh0A[k * 8 + r * 2] = pack2(v, v);
    }
    float xr0 = 0.f, xr1 = 0.f;
    const int i0 = tid, i1 = tid + 288;
    if (isA) {
        xr0 = x[((size_t)(b0 + (i0 >> 7)) * TT + 1) * IND + (i0 & 127)];
        if (i1 < ROWS * IND)
            xr1 = x[((size_t)(b0 + (i1 >> 7)) * TT + 1) * IND + (i1 & 127)];
    }

    __syncthreads();
    asm volatile("barrier.cluster.arrive.aligned;" ::: "memory");
    asm volatile("barrier.cluster.wait.aligned;" ::: "memory");

    if (isA) {
        // =================== STAGE A : layer 0 ===================
        const ulonglong2* WbaseA = (const ulonglong2*)
            (g_W0f[rank] + (size_t)(kcA * 56) * RS0 + comboA * 4);
        for (int t = 0; t < TT; ++t) {
            const int pr = t & 1, pw = (t + 1) & 1;
            float* xh0r = xh0A + pr * XB0F;
            float* xh0w = xh0A + pw * XB0F;
            float* xh1c = xh1A + pr * XB1F;

            if (t >= 1)
                mbar_wait(sbase + MB_RDYA((t - 1) & 1) * 4, ((t - 1) >> 1) & 1);

            if (actA) {
                const ulonglong2* Wp = WbaseA;
                const float* ab = xh0r + (kcA * 56) * 8;
                ull aA0 = 0, aB0 = 0, aA1 = 0, aB1 = 0;
                ull aA2 = 0, aB2 = 0, aA3 = 0, aB3 = 0;
                #pragma unroll 8
                for (int k = 0; k < 56; ++k) {
                    ulonglong2 w   = Wp[k * (RS0 / 4)];
                    ulonglong2 d01 = *(const ulonglong2*)(ab + k * 8);
                    ulonglong2 d23 = *(const ulonglong2*)(ab + k * 8 + 4);
                    aA0 = fma2(w.x, d01.x, aA0); aB0 = fma2(w.y, d01.x, aB0);
                    aA1 = fma2(w.x, d01.y, aA1); aB1 = fma2(w.y, d01.y, aB1);
                    aA2 = fma2(w.x, d23.x, aA2); aB2 = fma2(w.y, d23.x, aB2);
                    aA3 = fma2(w.x, d23.y, aA3); aB3 = fma2(w.y, d23.y, aB3);
                }
                float* P = partA + (size_t)((kcA * 3 + matA) * 4) * 80 + jgA * 4;
                *(ulonglong2*)(P)       = make_ulonglong2(aA0, aB0);
                *(ulonglong2*)(P + 80)  = make_ulonglong2(aA1, aB1);
                *(ulonglong2*)(P + 160) = make_ulonglong2(aA2, aB2);
                *(ulonglong2*)(P + 240) = make_ulonglong2(aA3, aB3);
            }
            BARN(1, 288);

            if (t >= 2)
                mbar_wait(sbase + MB_CONB(t & 1) * 4, ((t - 2) >> 1) & 1);

            if (combA && cjA < nj0) {
                const int r0 = crA, r1 = crA + 1;
                float a1r0 = 0, a1r1 = 0, a2r0 = 0, a2r1 = 0, acr0 = 0, acr1 = 0;
                #pragma unroll
                for (int c = 0; c < 5; ++c) {
                    const float* P = partA + (size_t)(c * 12) * 80;
                    a1r0 += P[(0 * 4 + r0) * 80 + cjA];
                    a1r1 += P[(0 * 4 + r1) * 80 + cjA];
                    a2r0 += P[(1 * 4 + r0) * 80 + cjA];
                    a2r1 += P[(1 * 4 + r1) * 80 + cjA];
                    acr0 += P[(2 * 4 + r0) * 80 + cjA];
                    acr1 += P[(2 * 4 + r1) * 80 + cjA];
                }
                float h0v = cfc_mix(a1r0, a2r0, acr0, bA1, bA2, bAc);
                float h1v = cfc_mix(a1r1, a2r1, acr1, bA1, bA2, bAc);
                ull u0 = pack2(h0v, h0v), u1 = pack2(h1v, h1v);
                const int jg = jb0 + cjA;
                const int oX = (IND + jg) * 8;
                const int oH = jg * 8;
                *(ull*)&xh0w[oX + r0 * 2] = u0;
                *(ull*)&xh0w[oX + r1 * 2] = u1;
                *(ull*)&xh1c[oH + r0 * 2] = u0;
                *(ull*)&xh1c[oH + r1 * 2] = u1;
                st_peer_u64(sbase + (OFF_XH0 + pw * XB0F + oX + r0 * 2) * 4, peer, u0);
                st_peer_u64(sbase + (OFF_XH0 + pw * XB0F + oX + r1 * 2) * 4, peer, u1);
                st_peer_u64(sbase + (OFF_XH1 + pr * XB1F + oH + r0 * 2) * 4, peer, u0);
                st_peer_u64(sbase + (OFF_XH1 + pr * XB1F + oH + r1 * 2) * 4, peer, u1);
            }
            *(ull*)&xh0w[(i0 & 127) * 8 + (i0 >> 7) * 2] = pack2(xr0, xr0);
            if (i1 < ROWS * IND)
                *(ull*)&xh0w[(i1 & 127) * 8 + (i1 >> 7) * 2] = pack2(xr1, xr1);
            {
                int tn = t + 2; if (tn > TT - 1) tn = TT - 1;
                xr0 = x[((size_t)(b0 + (i0 >> 7)) * TT + tn) * IND + (i0 & 127)];
                if (i1 < ROWS * IND)
                    xr1 = x[((size_t)(b0 + (i1 >> 7)) * TT + tn) * IND + (i1 & 127)];
            }
            BARN(1, 288);
            if (tid == 0) {
                cfence();
                mbar_arrive_local(sbase + MB_RDYA(t & 1) * 4);
                mbar_arrive_peer(sbase + MB_RDYA(t & 1) * 4, peer);
            }
        }
    } else if (isB) {
        // =================== STAGE B : layer 1 ===================
        const ulonglong2* WbaseB = (const ulonglong2*)
            (g_W1f[rank] + (size_t)(kcB * 63) * RS1 + comboB * 4);
        for (int t = 0; t < TT; ++t) {
            const int pr = t & 1, pw = (t + 1) & 1;
            float* xh1r = xh1A + pr * XB1F;
            float* xh1w = xh1A + pw * XB1F;
            float* xh2c = xh2A + pr * XB2F;

            mbar_wait(sbase + MB_RDYA(t & 1) * 4, (t >> 1) & 1);
            if (t >= 1)
                mbar_wait(sbase + MB_RDYB((t - 1) & 1) * 4, ((t - 1) >> 1) & 1);

            if (actB) {
                const ulonglong2* Wp = WbaseB;
                const float* ab = xh1r + (kcB * 63) * 8;
                ull aA0 = 0, aB0 = 0, aA1 = 0, aB1 = 0;
                ull aA2 = 0, aB2 = 0, aA3 = 0, aB3 = 0;
                #pragma unroll 7
                for (int k = 0; k < 63; ++k) {
                    ulonglong2 w   = Wp[k * (RS1 / 4)];
                    ulonglong2 d01 = *(const ulonglong2*)(ab + k * 8);
                    ulonglong2 d23 = *(const ulonglong2*)(ab + k * 8 + 4);
                    aA0 = fma2(w.x, d01.x, aA0); aB0 = fma2(w.y, d01.x, aB0);
                    aA1 = fma2(w.x, d01.y, aA1); aB1 = fma2(w.y, d01.y, aB1);
                    aA2 = fma2(w.x, d23.x, aA2); aB2 = fma2(w.y, d23.x, aB2);
                    aA3 = fma2(w.x, d23.y, aA3); aB3 = fma2(w.y, d23.y, aB3);
                }
                float* P = partB + (size_t)((kcB * 3 + matB) * 4) * 56 + jgB * 4;
                *(ulonglong2*)(P)       = make_ulonglong2(aA0, aB0);
                *(ulonglong2*)(P + 56)  = make_ulonglong2(aA1, aB1);
                *(ulonglong2*)(P + 112) = make_ulonglong2(aA2, aB2);
                *(ulonglong2*)(P + 168) = make_ulonglong2(aA3, aB3);
            }
            BARN(2, 160);
            if (bt == 0) {
                mbar_arrive_local(sbase + MB_CONB(t & 1) * 4);
                mbar_arrive_peer(sbase + MB_CONB(t & 1) * 4, peer);
            }
            if (t >= 2)
                mbar_wait(sbase + MB_CONC(t & 1) * 4, ((t - 2) >> 1) & 1);

            if (combB && cjB < nj1) {
                const int r0 = crB, r1 = crB + 1;
                float a1r0 = 0, a1r1 = 0, a2r0 = 0, a2r1 = 0, acr0 = 0, acr1 = 0;
                #pragma unroll
                for (int c = 0; c < 4; ++c) {
                    const float* P = partB + (size_t)(c * 12) * 56;
                    a1r0 += P[(0 * 4 + r0) * 56 + cjB];
                    a1r1 += P[(0 * 4 + r1) * 56 + cjB];
                    a2r0 += P[(1 * 4 + r0) * 56 + cjB];
                    a2r1 += P[(1 * 4 + r1) * 56 + cjB];
                    acr0 += P[(2 * 4 + r0) * 56 + cjB];
                    acr1 += P[(2 * 4 + r1) * 56 + cjB];
                }
                float h0v = cfc_mix(a1r0, a2r0, acr0, bB1, bB2, bBc);
                float h1v = cfc_mix(a1r1, a2r1, acr1, bB1, bB2, bBc);
                ull u0 = pack2(h0v, h0v), u1 = pack2(h1v, h1v);
                const int jg = jb1 + cjB;
                const int oH = (NI + jg) * 8;
                const int o2 = jg * 4;
                *(ull*)&xh1w[oH + r0 * 2] = u0;
                *(ull*)&xh1w[oH + r1 * 2] = u1;
                xh2c[o2 + r0] = h0v;
                xh2c[o2 + r1] = h1v;
                st_peer_u64(sbase + (OFF_XH1 + pw * XB1F + oH + r0 * 2) * 4, peer, u0);
                st_peer_u64(sbase + (OFF_XH1 + pw * XB1F + oH + r1 * 2) * 4, peer, u1);
                st_peer_u32(sbase + (OFF_XH2 + pr * XB2F + o2 + r0) * 4, peer, h0v);
                st_peer_u32(sbase + (OFF_XH2 + pr * XB2F + o2 + r1) * 4, peer, h1v);
            }
            BARN(2, 160);
            if (bt == 0) {
                cfence();
                mbar_arrive_local(sbase + MB_RDYB(t & 1) * 4);
                mbar_arrive_peer(sbase + MB_RDYB(t & 1) * 4, peer);
            }
        }
    } else {
        // =================== STAGE C : layer 2 ===================
        for (int t = 0; t < TT; ++t) {
            const int pr = t & 1, pw = (t + 1) & 1;
            float* xh2r = xh2A + pr * XB2F;
            float* xh2w = xh2A + pw * XB2F;

            mbar_wait(sbase + MB_RDYB(t & 1) * 4, (t >> 1) & 1);

            ull acc01 = 0, acc23 = 0;
            if (actC) {
                const float* W = sw2 + matC * (CAT2 * 8) + jC;
                #pragma unroll 4
                for (int k = 0; k < CAT2; ++k) {
                    float w = W[k * 8];
                    ull ww = pack2(w, w);
                    ulonglong2 u = *(const ulonglong2*)(xh2r + k * 4);
                    acc01 = fma2(ww, u.x, acc01);
                    acc23 = fma2(ww, u.y, acc23);
                }
            }
            __syncwarp();
            if (ct == 0) {
                mbar_arrive_local(sbase + MB_CONC(t & 1) * 4);
                mbar_arrive_peer(sbase + MB_CONC(t & 1) * 4, peer);
            }
            ull m1_01 = __shfl_sync(0xffffffffu, acc01, 8 + jC);
            ull m1_23 = __shfl_sync(0xffffffffu, acc23, 8 + jC);
            ull m2_01 = __shfl_sync(0xffffffffu, acc01, 16 + jC);
            ull m2_23 = __shfl_sync(0xffffffffu, acc23, 16 + jC);
            if (ct < 8) {
                float a1[4], a2[4], ac[4];
                unpack2(acc01, a1[0], a1[1]); unpack2(acc23, a1[2], a1[3]);
                unpack2(m1_01, a2[0], a2[1]); unpack2(m1_23, a2[2], a2[3]);
                unpack2(m2_01, ac[0], ac[1]); unpack2(m2_23, ac[2], ac[3]);
                #pragma unroll
                for (int r = 0; r < 4; ++r) {
                    float h = cfc_mix(a1[r], a2[r], ac[r], bC1, bC2, bCc);
                    xh2w[(NCC + jC) * 4 + r] = h;
                    if (rank == 0)
                        out[((size_t)(b0 + r) * TT + t) * NM + jC] = tanhf(h);
                }
            }
            __syncwarp();
        }
    }

    __syncthreads();
    asm volatile("barrier.cluster.arrive.aligned;" ::: "memory");
    asm volatile("barrier.cluster.wait.aligned;" ::: "memory");
    cfence();

    if (write_h && rank == 0) {
        size_t base = (size_t)BB * TT * NM;
        for (int jt = tid; jt < 256; jt += NTH) {
            #pragma unroll
            for (int r = 0; r < 4; ++r) {
                float v;
                if (jt < NI)            v = xh0A[(IND + jt) * 8 + r * 2];
                else if (jt < NI + NCC) v = xh1A[(NI + (jt - NI)) * 8 + r * 2];
                else                    v = xh2A[(NCC + (jt - NI - NCC)) * 4 + r];
                out[base + (size_t)(b0 + r) * 256 + jt] = v;
            }
        }
    }
    asm volatile("barrier.cluster.arrive.aligned;" ::: "memory");
    asm volatile("barrier.cluster.wait.aligned;" ::: "memory");
}

// ---------------------------------------------------------------------------
extern "C" void kernel_launch(void* const* d_in, const int* in_sizes, int n_in,
                              void* d_out, int out_size)
{
    const float *x, *dt;
    const float *w1[3], *b1[3], *w2[3], *b2[3], *wa[3], *ba[3], *wb[3], *bb[3];
    const int   *m[3];

    if (in_sizes[0] == BB * TT * IND) {
        x  = (const float*)d_in[0];
        dt = (const float*)d_in[1];
        for (int l = 0; l < 3; l++) {
            int base = 2 + 9 * l;
            w1[l] = (const float*)d_in[base + 0];
            b1[l] = (const float*)d_in[base + 1];
            w2[l] = (const float*)d_in[base + 2];
            b2[l] = (const float*)d_in[base + 3];
            wa[l] = (const float*)d_in[base + 4];
            ba[l] = (const float*)d_in[base + 5];
            wb[l] = (const float*)d_in[base + 6];
            bb[l] = (const float*)d_in[base + 7];
            m[l]  = (const int*)  d_in[base + 8];
        }
    } else {
        for (int l = 0; l < 3; l++) {
            int base = 9 * l;
            w1[l] = (const float*)d_in[base + 0];
            w2[l] = (const float*)d_in[base + 1];
            wa[l] = (const float*)d_in[base + 2];
            wb[l] = (const float*)d_in[base + 3];
            b1[l] = (const float*)d_in[base + 4];
            b2[l] = (const float*)d_in[base + 5];
            ba[l] = (const float*)d_in[base + 6];
            bb[l] = (const float*)d_in[base + 7];
            m[l]  = (const int*)  d_in[base + 8];
        }
        x  = (const float*)d_in[27];
        dt = (const float*)d_in[28];
    }

    cfc_precompute_kernel<<<148, 256>>>(
        w1[0], w2[0], wa[0], wb[0], ba[0], bb[0], m[0],
        w1[1], w2[1], wa[1], wb[1], ba[1], bb[1], m[1],
        w1[2], w2[2], wa[2], wb[2], ba[2], bb[2], m[2],
        dt);

    cudaFuncSetAttribute(cfc_main_kernel,
                         cudaFuncAttributeMaxDynamicSharedMemorySize, SMEM_BYTES);

    int write_h = (out_size >= BB * TT * NM + BB * 256) ? 1 : 0;
    cfc_main_kernel<<<(BB / ROWS) * 2, NTH, SMEM_BYTES>>>(
        x, b1[0], b2[0], b1[1], b2[1], b1[2], b2[2],
        (float*)d_out, write_h);
}